// round 9
// baseline (speedup 1.0000x reference)
#include <cuda_runtime.h>
#include <cstdint>

#define MM 2048
#define NODE 64
#define TT 256
#define RB 8               // rows per CTA
#define NTHREADS 512
#define WROW 68            // row stride in floats: 272B, 16B-aligned, banks shift 4/row

// Scratch (no cudaMalloc allowed): softplus table
__device__ __align__(16) float st_g[TT * NODE];   // 64 KB, st_g[0][:]=1.0 (IN_SCALE)

// ---------------- phase 0: softplus table ----------------
__global__ void k_softplus(const float* __restrict__ ne) {
    int idx = blockIdx.x * blockDim.x + threadIdx.x;
    if (idx >= TT * NODE) return;
    int t = idx >> 6;
    int j = idx & 63;
    float v;
    if (t == 0) {
        v = 1.0f;  // IN_SCALE at t=0
    } else {
        float x = ne[j * TT + t];  // noise_embedding layout (1, NODE, T)
        v = fmaxf(x, 0.0f) + log1pf(expf(-fabsf(x)));  // stable softplus
    }
    st_g[idx] = v;
}

__device__ __forceinline__ void cp_async16(uint32_t dst, const void* src) {
    asm volatile("cp.async.cg.shared.global [%0], [%1], 16;\n" :: "r"(dst), "l"(src));
}
// Blackwell packed fp32x2 FMA: acc += a * b (elementwise on both 32-bit halves)
__device__ __forceinline__ void fma2(unsigned long long& acc,
                                     unsigned long long a, unsigned long long b) {
    asm volatile("fma.rn.f32x2 %0, %1, %2, %0;" : "+l"(acc) : "l"(a), "l"(b));
}
__device__ __forceinline__ unsigned long long pack2(float lo, float hi) {
    unsigned long long r;
    asm("mov.b64 %0, {%1, %2};" : "=l"(r) : "r"(__float_as_uint(lo)), "r"(__float_as_uint(hi)));
    return r;
}
__device__ __forceinline__ float hadd2(unsigned long long v) {
    unsigned int lo, hi;
    asm("mov.b64 {%0, %1}, %2;" : "=r"(lo), "=r"(hi) : "l"(v));
    return __uint_as_float(lo) + __uint_as_float(hi);
}

// ---------------- main: fused 255-step recurrence ----------------
__global__ void __launch_bounds__(NTHREADS, 2)
k_chain(const float* __restrict__ W,
        const float* __restrict__ b,
        const float* __restrict__ eps0,
        const float* __restrict__ eps,
        float* __restrict__ out)
{
    // W double buffer, ORIGINAL (j,k) layout, rows padded to 272B : 2 x 17.4 KB
    __shared__ float Wsh[2][NODE * WROW];
    // x double buffer, rows padded to 272B : 2 x 2.2 KB
    __shared__ float xs[2][RB * WROW];

    const int tid = threadIdx.x;
    const int w   = tid >> 5;             // 0..15
    const int ln  = tid & 31;
    const int r   = ln >> 2;              // 0..7 : row within CTA tile (all warps)
    const int gl  = ln & 3;               // 0..3 : column phase
    const int col = w * 4 + gl;           // 0..63 : this thread's single column
    const int m   = blockIdx.x * RB + r;

    float* __restrict__ outx = out;
    float* __restrict__ outm = out + (size_t)MM * NODE * TT;
    float* __restrict__ outs = out + 2 * (size_t)MM * NODE * TT;

    const uint32_t wsh_base = (uint32_t)__cvta_generic_to_shared(&Wsh[0][0]);
    const uint32_t WBUF = (uint32_t)(NODE * WROW * 4);   // bytes per W buffer

    // Prefetch W[1] into buffer 1 (buffer parity == t&1).
    // Chunk f (0..1023): j = f>>4, kc = f&15 ; 16B chunk of row j
    {
        const float* src = W + 4096;
        #pragma unroll
        for (int i = 0; i < 2; i++) {
            int f = tid + i * NTHREADS;
            int j = f >> 4, kc = f & 15;
            cp_async16(wsh_base + WBUF + (uint32_t)(j * (WROW * 4) + kc * 16),
                       src + j * 64 + kc * 4);
        }
        asm volatile("cp.async.commit_group;\n");
    }

    float xreg[8], mreg[8];   // 8-step output staging (registers)

    // ---- t = 0: x0 = eps0, m0 = 0 ----
    {
        float e0 = eps0[(size_t)m * NODE + col];
        xreg[0] = e0;  mreg[0] = 0.f;
        if (w < 4) {
            // one writer per (r, col): warps 0..3 cover gl-phase cols? No —
            // every thread has a unique (r, col) pair only within its warp's
            // col range; across warps cols differ, so all 512 writes are unique.
        }
        xs[0][r * WROW + col] = e0;
    }

    // Prefetch per-step vectors for t=1 (registers)
    float bv = b[64 + col];
    float sv = st_g[64 + col];
    float ev = eps[(size_t)m * NODE + col];

    #pragma unroll 1
    for (int t = 1; t < TT; ++t) {
        const int cur = (t - 1) & 1;
        const int nxt = t & 1;

        // 1) W[t] landed. 2) Barrier: retired buffer free, xs[cur] visible.
        asm volatile("cp.async.wait_group 0;\n");
        __syncthreads();
        // 3) Prefetch W[t+1] into the retired buffer (overlaps FMA block).
        if (t + 1 < TT) {
            const float* src = W + (size_t)(t + 1) * 4096;
            uint32_t dstb = wsh_base + (uint32_t)((t + 1) & 1) * WBUF;
            #pragma unroll
            for (int i = 0; i < 2; i++) {
                int f = tid + i * NTHREADS;
                int j = f >> 4, kc = f & 15;
                cp_async16(dstb + (uint32_t)(j * (WROW * 4) + kc * 16),
                           src + j * 64 + kc * 4);
            }
            asm volatile("cp.async.commit_group;\n");
        }

        // Prefetch per-step vectors for t+1 (hides DRAM latency under FMAs)
        const int tp = (t + 1 < TT) ? (t + 1) : t;
        float bn = b[tp * 64 + col];
        float sn = st_g[tp * 64 + col];
        float en = eps[((size_t)(tp - 1) * MM + m) * NODE + col];

        // Packed even/odd-k accumulation: acc = (b + sum_even_k, sum_odd_k)
        unsigned long long acc = pack2(bv, 0.f);

        const float* xrow = &xs[cur][r * WROW];
        const float* wr   = &Wsh[nxt][col * WROW];  // lane col deltas {0,1,2,3}
                                                    // -> 4 distinct addrs, 8x bcast
        #pragma unroll
        for (int kc = 0; kc < 16; ++kc) {
            ulonglong2 xp = *(const ulonglong2*)(xrow + kc * 4);  // (x0,x1),(x2,x3)
            ulonglong2 wv = *(const ulonglong2*)(wr + kc * 4);
            fma2(acc, xp.x, wv.x);
            fma2(acc, xp.y, wv.y);
        }

        float a  = hadd2(acc);
        float xv = a + sv * ev;

        const int tl = t & 7;
        mreg[tl] = a;
        xreg[tl] = xv;
        xs[nxt][r * WROW + col] = xv;   // 32 distinct banks across warp

        bv = bn; sv = sn; ev = en;

        // ---- flush every 8 steps: reversed, 32B-aligned float4 pairs ----
        if (tl == 7) {
            const int cch   = t >> 3;            // chunk id, 0..31
            const int obase = 248 - 8 * cch;     // out offset of t = 8c+7 .. 8c
            const float* sp = st_g + (8 * cch) * NODE + col;
            size_t base = ((size_t)m * NODE + col) * TT + obase;
            *(float4*)(outx + base)     = make_float4(xreg[7], xreg[6], xreg[5], xreg[4]);
            *(float4*)(outx + base + 4) = make_float4(xreg[3], xreg[2], xreg[1], xreg[0]);
            *(float4*)(outm + base)     = make_float4(mreg[7], mreg[6], mreg[5], mreg[4]);
            *(float4*)(outm + base + 4) = make_float4(mreg[3], mreg[2], mreg[1], mreg[0]);
            *(float4*)(outs + base)     = make_float4(sp[7 * NODE], sp[6 * NODE], sp[5 * NODE], sp[4 * NODE]);
            *(float4*)(outs + base + 4) = make_float4(sp[3 * NODE], sp[2 * NODE], sp[1 * NODE], sp[0]);
        }
    }
}

extern "C" void kernel_launch(void* const* d_in, const int* in_sizes, int n_in,
                              void* d_out, int out_size) {
    const float* W    = (const float*)d_in[0];   // (T, NODE, NODE)
    const float* b    = (const float*)d_in[1];   // (T, NODE)
    const float* ne   = (const float*)d_in[2];   // (1, NODE, T)
    const float* eps0 = (const float*)d_in[3];   // (M, NODE)
    const float* eps  = (const float*)d_in[4];   // (T-1, M, NODE)
    float* out = (float*)d_out;                  // [x | m | s], each (M, NODE, T)

    k_softplus<<<(TT * NODE + 255) / 256, 256>>>(ne);
    k_chain<<<MM / RB, NTHREADS>>>(W, b, eps0, eps, out);
}